// round 8
// baseline (speedup 1.0000x reference)
#include <cuda_runtime.h>
#include <math.h>

// Problem dims
#define NB 256      // batch
#define NT 512      // time steps
#define ND 64       // input dim
#define NH 512      // hidden
#define NC 64       // fc out
#define KTOT 576    // NH + ND (fused K dimension)
#define DTF 0.1f

// Step-GEMM tiling
#define BM 32
#define BH 32
#define BK 16
#define NITER (KTOT / BK)     // 36
#define STEP_THREADS 128

// FC tiling
#define FBM 64

// Scratch (static device globals only — no allocation allowed)
__device__ float g_B[KTOT * 1024];   // [k][n], n = (h/2)*4 + {z0,z1,v0,v1}
__device__ float g_fcT[NH * NC];     // fc_w transposed: [k][c]

// ---------------------------------------------------------------------------
// Packed fp32x2 FMA (Blackwell). d += a * b elementwise on a float2 packed in u64.
// ---------------------------------------------------------------------------
__device__ __forceinline__ void fma2(unsigned long long &d,
                                     unsigned long long a,
                                     unsigned long long b) {
    asm("fma.rn.f32x2 %0, %1, %2, %0;" : "+l"(d) : "l"(a), "l"(b));
}
__device__ __forceinline__ float2 u2f(unsigned long long u) {
    float2 r;
    asm("mov.b64 {%0, %1}, %2;" : "=f"(r.x), "=f"(r.y) : "l"(u));
    return r;
}

// ---------------------------------------------------------------------------
// Prep: build fused weight matrix g_B and transposed fc weights g_fcT.
//   g_B[k][n]: n = 4*h2 + j, h = 2*h2 + (j&1), j<2 -> z-weights, j>=2 -> v-weights
//   k <  NH : z: K[h][k],       v: W[h][k]
//   k >= NH : z: P_z[h][k-NH],  v: Pm[h][k-NH]  (Pm = P rows < NH/2, else 0)
// ---------------------------------------------------------------------------
__global__ void prep_kernel(const float* __restrict__ W,  const float* __restrict__ P,
                            const float* __restrict__ Kw, const float* __restrict__ Pz,
                            const float* __restrict__ fcw) {
    int idx = blockIdx.x * blockDim.x + threadIdx.x;
    const int totalB = KTOT * 1024;
    if (idx < totalB) {
        int k = idx >> 10;
        int n = idx & 1023;
        int h = ((n >> 2) << 1) | (n & 1);
        bool isv = (n & 2) != 0;
        float val;
        if (k < NH) {
            val = isv ? W[h * NH + k] : Kw[h * NH + k];
        } else {
            int d = k - NH;
            val = isv ? ((h < NH / 2) ? P[h * ND + d] : 0.0f)
                      : Pz[h * ND + d];
        }
        g_B[idx] = val;
    } else {
        int j = idx - totalB;
        if (j < NH * NC) {
            int k = j >> 6;
            int c = j & 63;
            g_fcT[j] = fcw[c * NH + k];
        }
    }
}

// ---------------------------------------------------------------------------
// One recurrence step t:
//   A[m][k] = k<NH ? relu(hid[m, t-1, k]) : x[m, t, k-NH]
//   C = A @ g_B  (z-half and v-half interleaved)
//   z = sigmoid(Cz + bz); v_new = (1-z)*v_old + DT*(Cv + bv)
//   hid[m, t, h] = v_new
// Grid: (NH/BH=16, NB/BM=8) = 128 CTAs, 128 threads each.
// ---------------------------------------------------------------------------
__global__ void __launch_bounds__(STEP_THREADS)
step_kernel(const float* __restrict__ x,
            const float* __restrict__ bz_g,
            const float* __restrict__ bv_g,
            float* __restrict__ hid,
            int t)
{
    __shared__ __align__(16) float sA[2][BK][2 * BM];   // A duplicated: [k][2m]
    __shared__ __align__(16) float sB[2][BK][2 * BH];   // [k][(hloc/2)*4 + j]

    const int tid = threadIdx.x;
    const int h0 = blockIdx.x * BH;
    const int m0 = blockIdx.y * BM;
    const int tx = tid & 15;       // h-pair index (2h per thread)
    const int ty = tid >> 4;       // m-quad index (4m per thread)

    // loader index decomposition
    const int a_m = tid >> 2;             // 0..31
    const int a_k = (tid & 3) << 2;       // 0,4,8,12
    const int b_k = tid >> 3;             // 0..15
    const int b_q = (tid & 7) << 3;       // 0..56

    const int it0 = (t == 0) ? (NH / BK) : 0;   // t==0: relu(v0)=0, skip v part

    unsigned long long accz[4], accv[4];
#pragma unroll
    for (int i = 0; i < 4; i++) { accz[i] = 0ull; accv[i] = 0ull; }

    auto loadA = [&](int it, float4 &va) {
        int kt0 = it * BK;
        if (kt0 < NH) {
            const float* src = hid + ((size_t)(m0 + a_m) * NT + (t - 1)) * NH + kt0 + a_k;
            float4 v = *(const float4*)src;
            va.x = fmaxf(v.x, 0.0f); va.y = fmaxf(v.y, 0.0f);
            va.z = fmaxf(v.z, 0.0f); va.w = fmaxf(v.w, 0.0f);
        } else {
            const float* src = x + ((size_t)(m0 + a_m) * NT + t) * ND + (kt0 - NH) + a_k;
            va = *(const float4*)src;
        }
    };
    auto loadB = [&](int it, float4 &vb0, float4 &vb1) {
        const float* src = g_B + (size_t)(it * BK + b_k) * 1024 + (h0 << 1) + b_q;
        vb0 = ((const float4*)src)[0];
        vb1 = ((const float4*)src)[1];
    };
    auto stsA = [&](int buf, const float4 &va) {
#pragma unroll
        for (int i = 0; i < 4; i++) {
            float v = (&va.x)[i];
            *(float2*)&sA[buf][a_k + i][2 * a_m] = make_float2(v, v);
        }
    };
    auto stsB = [&](int buf, const float4 &vb0, const float4 &vb1) {
        *(float4*)&sB[buf][b_k][b_q]     = vb0;
        *(float4*)&sB[buf][b_k][b_q + 4] = vb1;
    };

    float4 rA, rB0, rB1;
    loadA(it0, rA); loadB(it0, rB0, rB1);
    stsA(0, rA); stsB(0, rB0, rB1);
    __syncthreads();

    int cur = 0;
    for (int it = it0; it < NITER; ++it) {
        const bool more = (it + 1) < NITER;
        if (more) { loadA(it + 1, rA); loadB(it + 1, rB0, rB1); }
#pragma unroll
        for (int kl = 0; kl < BK; ++kl) {
            const ulonglong2 aa0 = *(const ulonglong2*)&sA[cur][kl][8 * ty];
            const ulonglong2 aa1 = *(const ulonglong2*)&sA[cur][kl][8 * ty + 4];
            const ulonglong2 bb  = *(const ulonglong2*)&sB[cur][kl][4 * tx];
            fma2(accz[0], aa0.x, bb.x); fma2(accv[0], aa0.x, bb.y);
            fma2(accz[1], aa0.y, bb.x); fma2(accv[1], aa0.y, bb.y);
            fma2(accz[2], aa1.x, bb.x); fma2(accv[2], aa1.x, bb.y);
            fma2(accz[3], aa1.y, bb.x); fma2(accv[3], aa1.y, bb.y);
        }
        if (more) { stsA(cur ^ 1, rA); stsB(cur ^ 1, rB0, rB1); }
        __syncthreads();
        cur ^= 1;
    }

    // Epilogue: gate + state update + hidden write
    const int hb = h0 + 2 * tx;
    const float2 bz = *(const float2*)&bz_g[hb];
    const float2 bv = *(const float2*)&bv_g[hb];
#pragma unroll
    for (int i = 0; i < 4; i++) {
        const int m = m0 + 4 * ty + i;
        const float2 az = u2f(accz[i]);
        const float2 av = u2f(accv[i]);
        float2 vold = make_float2(0.0f, 0.0f);
        if (t > 0)
            vold = *(const float2*)&hid[((size_t)m * NT + (t - 1)) * NH + hb];
        // z = 10*DT*sigmoid(.) ; 10*0.1 == 1.0 exactly in f32
        const float z0 = 1.0f / (1.0f + expf(-(az.x + bz.x)));
        const float z1 = 1.0f / (1.0f + expf(-(az.y + bz.y)));
        const float vn0 = (1.0f - z0) * vold.x + DTF * (av.x + bv.x);
        const float vn1 = (1.0f - z1) * vold.y + DTF * (av.y + bv.y);
        *(float2*)&hid[((size_t)m * NT + t) * NH + hb] = make_float2(vn0, vn1);
    }
}

// ---------------------------------------------------------------------------
// FC: out[r][c] = hidden[r][:] . fc_w[c][:] + fc_b[c],  r in [0, NB*NT)
// Tiles: 64 rows x 64 cols, K staged by 16. Same f32x2 scheme.
// ---------------------------------------------------------------------------
__global__ void __launch_bounds__(128)
fc_kernel(const float* __restrict__ hid,
          const float* __restrict__ fcb,
          float* __restrict__ out)
{
    __shared__ __align__(16) float fA[2][16][2 * FBM];  // dup: [k][2m]
    __shared__ __align__(16) float fB[2][16][NC];       // [k][c]

    const int tid = threadIdx.x;
    const int m0 = blockIdx.x * FBM;
    const int tx = tid & 7;        // c octet (8 c per thread)
    const int ty = tid >> 3;       // 0..15 (4 m per thread)
    const int c0 = tx * 8;

    const int a_m = tid >> 1;            // 0..63
    const int a_k = (tid & 1) * 8;       // 0 or 8
    const int b_k = tid >> 3;            // 0..15
    const int b_q = (tid & 7) * 8;       // 0..56

    unsigned long long acc[4][4];
#pragma unroll
    for (int i = 0; i < 4; i++)
#pragma unroll
        for (int j = 0; j < 4; j++) acc[i][j] = 0ull;

    auto loadA = [&](int it, float4 &v0, float4 &v1) {
        const float* src = hid + (size_t)(m0 + a_m) * NH + it * 16 + a_k;
        v0 = ((const float4*)src)[0];
        v1 = ((const float4*)src)[1];
    };
    auto loadB = [&](int it, float4 &v0, float4 &v1) {
        const float* src = g_fcT + (size_t)(it * 16 + b_k) * NC + b_q;
        v0 = ((const float4*)src)[0];
        v1 = ((const float4*)src)[1];
    };
    auto stsA = [&](int buf, const float4 &v0, const float4 &v1) {
#pragma unroll
        for (int i = 0; i < 4; i++) {
            float a = (&v0.x)[i];
            *(float2*)&fA[buf][a_k + i][2 * a_m] = make_float2(a, a);
        }
#pragma unroll
        for (int i = 0; i < 4; i++) {
            float a = (&v1.x)[i];
            *(float2*)&fA[buf][a_k + 4 + i][2 * a_m] = make_float2(a, a);
        }
    };
    auto stsB = [&](int buf, const float4 &v0, const float4 &v1) {
        *(float4*)&fB[buf][b_k][b_q]     = v0;
        *(float4*)&fB[buf][b_k][b_q + 4] = v1;
    };

    float4 rA0, rA1, rB0, rB1;
    loadA(0, rA0, rA1); loadB(0, rB0, rB1);
    stsA(0, rA0, rA1); stsB(0, rB0, rB1);
    __syncthreads();

    int cur = 0;
    const int FNITER = NH / 16;   // 32
    for (int it = 0; it < FNITER; ++it) {
        const bool more = (it + 1) < FNITER;
        if (more) { loadA(it + 1, rA0, rA1); loadB(it + 1, rB0, rB1); }
#pragma unroll
        for (int kl = 0; kl < 16; ++kl) {
            const ulonglong2 aa0 = *(const ulonglong2*)&fA[cur][kl][8 * ty];
            const ulonglong2 aa1 = *(const ulonglong2*)&fA[cur][kl][8 * ty + 4];
            const ulonglong2 bb0 = *(const ulonglong2*)&fB[cur][kl][c0];
            const ulonglong2 bb1 = *(const ulonglong2*)&fB[cur][kl][c0 + 4];
            fma2(acc[0][0], aa0.x, bb0.x); fma2(acc[0][1], aa0.x, bb0.y);
            fma2(acc[0][2], aa0.x, bb1.x); fma2(acc[0][3], aa0.x, bb1.y);
            fma2(acc[1][0], aa0.y, bb0.x); fma2(acc[1][1], aa0.y, bb0.y);
            fma2(acc[1][2], aa0.y, bb1.x); fma2(acc[1][3], aa0.y, bb1.y);
            fma2(acc[2][0], aa1.x, bb0.x); fma2(acc[2][1], aa1.x, bb0.y);
            fma2(acc[2][2], aa1.x, bb1.x); fma2(acc[2][3], aa1.x, bb1.y);
            fma2(acc[3][0], aa1.y, bb0.x); fma2(acc[3][1], aa1.y, bb0.y);
            fma2(acc[3][2], aa1.y, bb1.x); fma2(acc[3][3], aa1.y, bb1.y);
        }
        if (more) { stsA(cur ^ 1, rA0, rA1); stsB(cur ^ 1, rB0, rB1); }
        __syncthreads();
        cur ^= 1;
    }

    const float4 fb0 = *(const float4*)&fcb[c0];
    const float4 fb1 = *(const float4*)&fcb[c0 + 4];
#pragma unroll
    for (int i = 0; i < 4; i++) {
        const int m = m0 + 4 * ty + i;
        const float2 p0 = u2f(acc[i][0]);
        const float2 p1 = u2f(acc[i][1]);
        const float2 p2 = u2f(acc[i][2]);
        const float2 p3 = u2f(acc[i][3]);
        float4 o0 = make_float4(p0.x + fb0.x, p0.y + fb0.y, p1.x + fb0.z, p1.y + fb0.w);
        float4 o1 = make_float4(p2.x + fb1.x, p2.y + fb1.y, p3.x + fb1.z, p3.y + fb1.w);
        float* dst = out + (size_t)m * NC + c0;
        ((float4*)dst)[0] = o0;
        ((float4*)dst)[1] = o1;
    }
}

// ---------------------------------------------------------------------------
// kernel_launch: prep + 512 sequential step launches + FC. Graph-capturable,
// allocation-free (scratch in __device__ globals), deterministic.
// Output layout: [out (B,T,C) fp32 | hidden (B,T,H) fp32]
// ---------------------------------------------------------------------------
extern "C" void kernel_launch(void* const* d_in, const int* in_sizes, int n_in,
                              void* d_out, int out_size)
{
    const float* x   = (const float*)d_in[0];
    const float* W   = (const float*)d_in[1];
    const float* P   = (const float*)d_in[2];
    const float* b_v = (const float*)d_in[3];
    const float* b_z = (const float*)d_in[4];
    const float* Kw  = (const float*)d_in[5];
    const float* Pz  = (const float*)d_in[6];
    const float* fcw = (const float*)d_in[7];
    const float* fcb = (const float*)d_in[8];

    float* out = (float*)d_out;
    float* hid = out + (size_t)NB * NT * NC;   // hidden region follows out

    (void)in_sizes; (void)n_in; (void)out_size;

    prep_kernel<<<(KTOT * 1024 + NH * NC + 255) / 256, 256>>>(W, P, Kw, Pz, fcw);

    dim3 sgrid(NH / BH, NB / BM);   // (16, 8) = 128 CTAs
    for (int t = 0; t < NT; ++t)
        step_kernel<<<sgrid, STEP_THREADS>>>(x, b_z, b_v, hid, t);

    fc_kernel<<<(NB * NT) / FBM, 128>>>(hid, fcb, out);
}

// round 9
// speedup vs baseline: 1.5573x; 1.5573x over previous
#include <cuda_runtime.h>
#include <math.h>
#include <stdint.h>

// Problem dims
#define NB 256
#define NT 512
#define ND 64
#define NH 512
#define NC 64
#define KTOT 576
#define DTF 0.1f

// Step-GEMM config: CTA tile 64m x 16h (32 zv-cols), grid (32,4)=128 CTAs
#define BK 32
#define NITER (KTOT / BK)      // 18
#define TPB 256
#define BM 64
#define BHC 32                 // interleaved zv columns per CTA
#define SMEM_FLOATS (3*BK*128 + 3*BK*BHC)
#define SMEM_BYTES  (SMEM_FLOATS * 4)   // 61440

// FC tiling
#define FBM 64

// Static scratch (no allocation allowed)
__device__ float g_B[KTOT * 1024];            // [k][n], n=(h/2)*4+{z0,z1,v0,v1}
__device__ float g_xdup[NT * ND * 2 * NB];    // [t][d][2m]  x duplicated  (67MB)
__device__ float g_rdup[2 * NH * 2 * NB];     // [slot][h][2m] relu(v) duplicated
__device__ float g_fcT[NH * NC];              // fc_w transposed [k][c]

// ---------------------------------------------------------------------------
__device__ __forceinline__ void fma2(unsigned long long &d,
                                     unsigned long long a,
                                     unsigned long long b) {
    asm("fma.rn.f32x2 %0, %1, %2, %0;" : "+l"(d) : "l"(a), "l"(b));
}
__device__ __forceinline__ float2 u2f(unsigned long long u) {
    float2 r;
    asm("mov.b64 {%0, %1}, %2;" : "=f"(r.x), "=f"(r.y) : "l"(u));
    return r;
}
__device__ __forceinline__ void cp16(uint32_t dst, const void* src) {
    asm volatile("cp.async.cg.shared.global [%0], [%1], 16;" :: "r"(dst), "l"(src));
}

// ---------------------------------------------------------------------------
// Prep: fused weight matrix g_B + transposed fc weights.
// ---------------------------------------------------------------------------
__global__ void prep_kernel(const float* __restrict__ W,  const float* __restrict__ P,
                            const float* __restrict__ Kw, const float* __restrict__ Pz,
                            const float* __restrict__ fcw) {
    int idx = blockIdx.x * blockDim.x + threadIdx.x;
    const int totalB = KTOT * 1024;
    if (idx < totalB) {
        int k = idx >> 10;
        int n = idx & 1023;
        int h = ((n >> 2) << 1) | (n & 1);
        bool isv = (n & 2) != 0;
        float val;
        if (k < NH) {
            val = isv ? W[h * NH + k] : Kw[h * NH + k];
        } else {
            int d = k - NH;
            val = isv ? ((h < NH / 2) ? P[h * ND + d] : 0.0f)
                      : Pz[h * ND + d];
        }
        g_B[idx] = val;
    } else {
        int j = idx - totalB;
        if (j < NH * NC) {
            int k = j >> 6;
            int c = j & 63;
            g_fcT[j] = fcw[c * NH + k];
        }
    }
}

// ---------------------------------------------------------------------------
// Prep: x transposed+duplicated: g_xdup[t][d][2m] = x[m][t][d] (both copies).
// Block: one t, 32-m tile; smem transpose for coalescing both sides.
// ---------------------------------------------------------------------------
__global__ void __launch_bounds__(256)
prep_xdup(const float* __restrict__ x) {
    __shared__ float s[64][33];
    const int t  = blockIdx.x;
    const int m0 = blockIdx.y * 32;
    const int tid = threadIdx.x;
#pragma unroll
    for (int i = 0; i < 8; i++) {
        int idx = tid + i * 256;
        int ml = idx >> 6, d = idx & 63;
        s[d][ml] = x[((size_t)(m0 + ml) * NT + t) * ND + d];
    }
    __syncthreads();
#pragma unroll
    for (int i = 0; i < 8; i++) {
        int idx = tid + i * 256;
        int d = idx >> 5, ml = idx & 31;
        float v = s[d][ml];
        *(float2*)&g_xdup[((size_t)t * ND + d) * 512 + 2 * (m0 + ml)] = make_float2(v, v);
    }
}

// ---------------------------------------------------------------------------
// One recurrence step. A operand comes pre-relu'd/pre-duplicated from
// g_rdup (k<512) and g_xdup (k>=512). cp.async 3-stage pipeline.
// grid (32 h-tiles, 4 m-tiles), 256 threads.
// ---------------------------------------------------------------------------
__global__ void __launch_bounds__(TPB)
step_kernel(const float* __restrict__ bz_g,
            const float* __restrict__ bv_g,
            float* __restrict__ hid,
            int t)
{
    extern __shared__ float smem[];
    float* sA = smem;                 // [3][BK][128]
    float* sB = smem + 3 * BK * 128;  // [3][BK][32]

    const int tid = threadIdx.x;
    const int bx  = blockIdx.x;       // h-tile 0..31
    const int by  = blockIdx.y;       // m-tile 0..3
    const int m0  = by * BM;
    const int tx  = tid & 7;          // h-pair within tile
    const int ty  = tid >> 3;         // m-pair 0..31

    const int wslot = t & 1;
    const float* Ar = g_rdup + (size_t)((t + 1) & 1) * (NH * 512) + 2 * m0;
    const float* Ax = g_xdup + (size_t)t * ND * 512 + 2 * m0;
    const float* Bp = g_B + bx * BHC;

    const int it0 = (t == 0) ? (NH / BK) : 0;   // t==0: relu(v0)=0

    auto issue = [&](int stage, int it) {
        const float* arow = (it * BK < NH) ? (Ar + (size_t)it * BK * 512)
                                           : (Ax + (size_t)(it * BK - NH) * 512);
#pragma unroll
        for (int r = 0; r < 5; r++) {
            int id = tid + r * TPB;           // 0..1279
            if (id < 1024) {                  // A: 32 rows x 32 chunks
                int kk = id >> 5, c = (id & 31) << 2;
                uint32_t dst = (uint32_t)__cvta_generic_to_shared(
                    &sA[((stage * BK + kk) << 7) + c]);
                cp16(dst, arow + (size_t)kk * 512 + c);
            } else {                          // B: 32 rows x 8 chunks
                int j = id - 1024;
                int kk = j >> 3, c = (j & 7) << 2;
                uint32_t dst = (uint32_t)__cvta_generic_to_shared(
                    &sB[(stage * BK + kk) * BHC + c]);
                cp16(dst, Bp + (size_t)(it * BK + kk) * 1024 + c);
            }
        }
    };

    issue(0, it0);
    asm volatile("cp.async.commit_group;");
    issue(1, it0 + 1);
    asm volatile("cp.async.commit_group;");

    unsigned long long az0 = 0, av0 = 0, az1 = 0, av1 = 0;

    int stage = 0;
    for (int it = it0; it < NITER; ++it) {
        asm volatile("cp.async.wait_group 1;");
        __syncthreads();
        const int nit = it + 2;
        if (nit < NITER) {
            int s2 = stage + 2; if (s2 >= 3) s2 -= 3;
            issue(s2, nit);
        }
        asm volatile("cp.async.commit_group;");   // always commit (keeps count)

        const float* pa = sA + ((stage * BK) << 7) + (ty << 2);
        const float* pb = sB + stage * BK * BHC + (tx << 2);
#pragma unroll
        for (int kk = 0; kk < BK; ++kk) {
            const ulonglong2 aa = *(const ulonglong2*)(pa + (kk << 7));
            const ulonglong2 bb = *(const ulonglong2*)(pb + kk * BHC);
            fma2(az0, aa.x, bb.x); fma2(av0, aa.x, bb.y);
            fma2(az1, aa.y, bb.x); fma2(av1, aa.y, bb.y);
        }
        stage = stage + 1; if (stage >= 3) stage -= 3;
    }

    // Epilogue: gate + state update; write hid and relu-dup for next step.
    const int h2 = bx * 8 + tx;
    const int hg = h2 * 2;
    const int mA = m0 + (ty << 1);

    const float2 bz = *(const float2*)&bz_g[hg];
    const float2 bv = *(const float2*)&bv_g[hg];
    const float2 azA = u2f(az0), avA = u2f(av0);
    const float2 azB = u2f(az1), avB = u2f(av1);

    float2 voA = make_float2(0.0f, 0.0f), voB = make_float2(0.0f, 0.0f);
    if (t > 0) {
        voA = *(const float2*)&hid[((size_t)mA * NT + (t - 1)) * NH + hg];
        voB = *(const float2*)&hid[((size_t)(mA + 1) * NT + (t - 1)) * NH + hg];
    }
    const float zA0 = 1.0f / (1.0f + expf(-(azA.x + bz.x)));
    const float zA1 = 1.0f / (1.0f + expf(-(azA.y + bz.y)));
    const float zB0 = 1.0f / (1.0f + expf(-(azB.x + bz.x)));
    const float zB1 = 1.0f / (1.0f + expf(-(azB.y + bz.y)));
    const float vA0 = (1.0f - zA0) * voA.x + DTF * (avA.x + bv.x);
    const float vA1 = (1.0f - zA1) * voA.y + DTF * (avA.y + bv.y);
    const float vB0 = (1.0f - zB0) * voB.x + DTF * (avB.x + bv.x);
    const float vB1 = (1.0f - zB1) * voB.y + DTF * (avB.y + bv.y);

    *(float2*)&hid[((size_t)mA * NT + t) * NH + hg]       = make_float2(vA0, vA1);
    *(float2*)&hid[((size_t)(mA + 1) * NT + t) * NH + hg] = make_float2(vB0, vB1);

    const float rA0 = fmaxf(vA0, 0.0f), rA1 = fmaxf(vA1, 0.0f);
    const float rB0 = fmaxf(vB0, 0.0f), rB1 = fmaxf(vB1, 0.0f);
    float* rd = g_rdup + (size_t)wslot * (NH * 512);
    *(float4*)&rd[(size_t)hg * 512 + 2 * mA]       = make_float4(rA0, rA0, rB0, rB0);
    *(float4*)&rd[(size_t)(hg + 1) * 512 + 2 * mA] = make_float4(rA1, rA1, rB1, rB1);
}

// ---------------------------------------------------------------------------
// FC: out[r][c] = hidden[r][:] . fc_w[c][:] + fc_b[c]  (unchanged from R7/8)
// ---------------------------------------------------------------------------
__global__ void __launch_bounds__(128)
fc_kernel(const float* __restrict__ hid,
          const float* __restrict__ fcb,
          float* __restrict__ out)
{
    __shared__ __align__(16) float fA[2][16][2 * FBM];
    __shared__ __align__(16) float fB[2][16][NC];

    const int tid = threadIdx.x;
    const int m0 = blockIdx.x * FBM;
    const int tx = tid & 7;
    const int ty = tid >> 3;
    const int c0 = tx * 8;

    const int a_m = tid >> 1;
    const int a_k = (tid & 1) * 8;
    const int b_k = tid >> 3;
    const int b_q = (tid & 7) * 8;

    unsigned long long acc[4][4];
#pragma unroll
    for (int i = 0; i < 4; i++)
#pragma unroll
        for (int j = 0; j < 4; j++) acc[i][j] = 0ull;

    auto loadA = [&](int it, float4 &v0, float4 &v1) {
        const float* src = hid + (size_t)(m0 + a_m) * NH + it * 16 + a_k;
        v0 = ((const float4*)src)[0];
        v1 = ((const float4*)src)[1];
    };
    auto loadB = [&](int it, float4 &v0, float4 &v1) {
        const float* src = g_fcT + (size_t)(it * 16 + b_k) * NC + b_q;
        v0 = ((const float4*)src)[0];
        v1 = ((const float4*)src)[1];
    };
    auto stsA = [&](int buf, const float4 &v0, const float4 &v1) {
#pragma unroll
        for (int i = 0; i < 4; i++) {
            float a = (&v0.x)[i];
            *(float2*)&fA[buf][a_k + i][2 * a_m] = make_float2(a, a);
        }
#pragma unroll
        for (int i = 0; i < 4; i++) {
            float a = (&v1.x)[i];
            *(float2*)&fA[buf][a_k + 4 + i][2 * a_m] = make_float2(a, a);
        }
    };
    auto stsB = [&](int buf, const float4 &v0, const float4 &v1) {
        *(float4*)&fB[buf][b_k][b_q]     = v0;
        *(float4*)&fB[buf][b_k][b_q + 4] = v1;
    };

    float4 rA0, rA1, rB0, rB1;
    loadA(0, rA0, rA1); loadB(0, rB0, rB1);
    stsA(0, rA0, rA1); stsB(0, rB0, rB1);
    __syncthreads();

    int cur = 0;
    const int FNITER = NH / 16;
    for (int it = 0; it < FNITER; ++it) {
        const bool more = (it + 1) < FNITER;
        if (more) { loadA(it + 1, rA0, rA1); loadB(it + 1, rB0, rB1); }
#pragma unroll
        for (int kl = 0; kl < 16; ++kl) {
            const ulonglong2 aa0 = *(const ulonglong2*)&fA[cur][kl][8 * ty];
            const ulonglong2 aa1 = *(const ulonglong2*)&fA[cur][kl][8 * ty + 4];
            const ulonglong2 bb0 = *(const ulonglong2*)&fB[cur][kl][c0];
            const ulonglong2 bb1 = *(const ulonglong2*)&fB[cur][kl][c0 + 4];
            fma2(acc[0][0], aa0.x, bb0.x); fma2(acc[0][1], aa0.x, bb0.y);
            fma2(acc[0][2], aa0.x, bb1.x); fma2(acc[0][3], aa0.x, bb1.y);
            fma2(acc[1][0], aa0.y, bb0.x); fma2(acc[1][1], aa0.y, bb0.y);
            fma2(acc[1][2], aa0.y, bb1.x); fma2(acc[1][3], aa0.y, bb1.y);
            fma2(acc[2][0], aa1.x, bb0.x); fma2(acc[2][1], aa1.x, bb0.y);
            fma2(acc[2][2], aa1.x, bb1.x); fma2(acc[2][3], aa1.x, bb1.y);
            fma2(acc[3][0], aa1.y, bb0.x); fma2(acc[3][1], aa1.y, bb0.y);
            fma2(acc[3][2], aa1.y, bb1.x); fma2(acc[3][3], aa1.y, bb1.y);
        }
        if (more) { stsA(cur ^ 1, rA0, rA1); stsB(cur ^ 1, rB0, rB1); }
        __syncthreads();
        cur ^= 1;
    }

    const float4 fb0 = *(const float4*)&fcb[c0];
    const float4 fb1 = *(const float4*)&fcb[c0 + 4];
#pragma unroll
    for (int i = 0; i < 4; i++) {
        const int m = m0 + 4 * ty + i;
        const float2 p0 = u2f(acc[i][0]);
        const float2 p1 = u2f(acc[i][1]);
        const float2 p2 = u2f(acc[i][2]);
        const float2 p3 = u2f(acc[i][3]);
        float4 o0 = make_float4(p0.x + fb0.x, p0.y + fb0.y, p1.x + fb0.z, p1.y + fb0.w);
        float4 o1 = make_float4(p2.x + fb1.x, p2.y + fb1.y, p3.x + fb1.z, p3.y + fb1.w);
        float* dst = out + (size_t)m * NC + c0;
        ((float4*)dst)[0] = o0;
        ((float4*)dst)[1] = o1;
    }
}

// ---------------------------------------------------------------------------
extern "C" void kernel_launch(void* const* d_in, const int* in_sizes, int n_in,
                              void* d_out, int out_size)
{
    const float* x   = (const float*)d_in[0];
    const float* W   = (const float*)d_in[1];
    const float* P   = (const float*)d_in[2];
    const float* b_v = (const float*)d_in[3];
    const float* b_z = (const float*)d_in[4];
    const float* Kw  = (const float*)d_in[5];
    const float* Pz  = (const float*)d_in[6];
    const float* fcw = (const float*)d_in[7];
    const float* fcb = (const float*)d_in[8];

    float* out = (float*)d_out;
    float* hid = out + (size_t)NB * NT * NC;

    (void)in_sizes; (void)n_in; (void)out_size;

    cudaFuncSetAttribute(step_kernel,
                         cudaFuncAttributeMaxDynamicSharedMemorySize, SMEM_BYTES);

    prep_kernel<<<(KTOT * 1024 + NH * NC + 255) / 256, 256>>>(W, P, Kw, Pz, fcw);
    prep_xdup<<<dim3(NT, NB / 32), 256>>>(x);

    dim3 sgrid(32, 4);   // 128 CTAs
    for (int t = 0; t < NT; ++t)
        step_kernel<<<sgrid, TPB, SMEM_BYTES>>>(b_z, b_v, hid, t);

    fc_kernel<<<(NB * NT) / FBM, 128>>>(hid, fcb, out);
}

// round 10
// speedup vs baseline: 1.7004x; 1.0919x over previous
#include <cuda_runtime.h>
#include <math.h>
#include <stdint.h>

// Problem dims
#define NB 256
#define NT 512
#define ND 64
#define NH 512
#define NC 64
#define DTF 0.1f

// Scan kernel config: grid (32 h-tiles, 4 m-tiles) = 128 CTAs, 256 threads
#define BK 32
#define TPB 256
#define BM 64
#define BHC 32                  // interleaved zv columns per CTA
#define NCTA 128
#define SMEM_FLOATS (576*BHC + 3*BK*128)
#define SMEM_BYTES  (SMEM_FLOATS * 4)    // 122880

// FC tiling
#define FBM 64

// Static scratch (no allocation allowed)
__device__ float g_B[576 * 1024];             // [k][n], n=(h/2)*4+{z0,z1,v0,v1}
__device__ float g_xdup[NT * ND * 2 * NB];    // [t][d][2m]  x duplicated
__device__ float g_rdup[2 * NH * 2 * NB];     // [slot][h][2m] relu(v) duplicated
__device__ float g_fcT[NH * NC];              // fc_w transposed [k][c]
__device__ unsigned int g_bar;                // scan barrier counter

// ---------------------------------------------------------------------------
__device__ __forceinline__ void fma2(unsigned long long &d,
                                     unsigned long long a,
                                     unsigned long long b) {
    asm("fma.rn.f32x2 %0, %1, %2, %0;" : "+l"(d) : "l"(a), "l"(b));
}
__device__ __forceinline__ float2 u2f(unsigned long long u) {
    float2 r;
    asm("mov.b64 {%0, %1}, %2;" : "=f"(r.x), "=f"(r.y) : "l"(u));
    return r;
}
__device__ __forceinline__ void cp16(uint32_t dst, const void* src) {
    asm volatile("cp.async.cg.shared.global [%0], [%1], 16;" :: "r"(dst), "l"(src));
}

// ---------------------------------------------------------------------------
// Prep: fused weight matrix g_B + transposed fc weights + barrier reset.
// ---------------------------------------------------------------------------
__global__ void prep_kernel(const float* __restrict__ W,  const float* __restrict__ P,
                            const float* __restrict__ Kw, const float* __restrict__ Pz,
                            const float* __restrict__ fcw) {
    int idx = blockIdx.x * blockDim.x + threadIdx.x;
    if (idx == 0) g_bar = 0u;                 // reset scan barrier each launch
    const int totalB = 576 * 1024;
    if (idx < totalB) {
        int k = idx >> 10;
        int n = idx & 1023;
        int h = ((n >> 2) << 1) | (n & 1);
        bool isv = (n & 2) != 0;
        float val;
        if (k < NH) {
            val = isv ? W[h * NH + k] : Kw[h * NH + k];
        } else {
            int d = k - NH;
            val = isv ? ((h < NH / 2) ? P[h * ND + d] : 0.0f)
                      : Pz[h * ND + d];
        }
        g_B[idx] = val;
    } else {
        int j = idx - totalB;
        if (j < NH * NC) {
            int k = j >> 6;
            int c = j & 63;
            g_fcT[j] = fcw[c * NH + k];
        }
    }
}

// ---------------------------------------------------------------------------
// Prep: x transposed+duplicated: g_xdup[t][d][2m] = x[m][t][d] (both copies).
// ---------------------------------------------------------------------------
__global__ void __launch_bounds__(256)
prep_xdup(const float* __restrict__ x) {
    __shared__ float s[64][33];
    const int t  = blockIdx.x;
    const int m0 = blockIdx.y * 32;
    const int tid = threadIdx.x;
#pragma unroll
    for (int i = 0; i < 8; i++) {
        int idx = tid + i * 256;
        int ml = idx >> 6, d = idx & 63;
        s[d][ml] = x[((size_t)(m0 + ml) * NT + t) * ND + d];
    }
    __syncthreads();
#pragma unroll
    for (int i = 0; i < 8; i++) {
        int idx = tid + i * 256;
        int d = idx >> 5, ml = idx & 31;
        float v = s[d][ml];
        *(float2*)&g_xdup[((size_t)t * ND + d) * 512 + 2 * (m0 + ml)] = make_float2(v, v);
    }
}

// ---------------------------------------------------------------------------
// Persistent scan kernel. One launch runs all 512 steps.
//  - B slice (576 x 32) resident in smem for the whole scan.
//  - v-state held in registers across steps.
//  - Steps separated by a device-wide spin barrier on g_bar (monotonic).
//  - A operand (relu-dup / x-dup) streamed via cp.async, 3-stage pipeline.
//  Iteration order per step: X chunks (k=512..575) first — issued BEFORE the
//  barrier spin — then the 16 recurrent chunks.
// ---------------------------------------------------------------------------
__global__ void __launch_bounds__(TPB)
scan_kernel(const float* __restrict__ bz_g,
            const float* __restrict__ bv_g,
            float* __restrict__ hid)
{
    extern __shared__ float smem[];
    float* sBf = smem;                 // [576][32]
    float* sA  = smem + 576 * BHC;     // [3][BK][128]

    const int tid = threadIdx.x;
    const int bx  = blockIdx.x;        // h-tile 0..31
    const int by  = blockIdx.y;        // m-tile 0..3
    const int m0  = by * BM;
    const int tx  = tid & 7;
    const int ty  = tid >> 3;

    // ---- load B slice into smem once (4608 x 16B) ----
#pragma unroll
    for (int r = 0; r < 18; r++) {
        int i = tid + r * TPB;
        int row = i >> 3, c = (i & 7) << 2;
        uint32_t dst = (uint32_t)__cvta_generic_to_shared(&sBf[row * BHC + c]);
        cp16(dst, g_B + (size_t)row * 1024 + bx * BHC + c);
    }
    asm volatile("cp.async.commit_group;");
    asm volatile("cp.async.wait_group 0;");
    __syncthreads();

    const int h2 = bx * 8 + tx;
    const int hg = h2 * 2;
    const float2 bz = *(const float2*)&bz_g[hg];
    const float2 bv = *(const float2*)&bv_g[hg];
    const int mA = m0 + (ty << 1);

    // v-state in registers
    float vA0 = 0.0f, vA1 = 0.0f, vB0 = 0.0f, vB1 = 0.0f;

    auto issueA = [&](int stg, const float* arow) {
#pragma unroll
        for (int r = 0; r < 4; r++) {
            int id = tid + r * TPB;                  // 0..1023
            int kk = id >> 5, c = (id & 31) << 2;
            uint32_t dst = (uint32_t)__cvta_generic_to_shared(
                &sA[(stg * BK + kk) * 128 + c]);
            cp16(dst, arow + (size_t)kk * 512 + c);
        }
    };

    for (int t = 0; t < NT; ++t) {
        const int niter = (t == 0) ? 2 : 18;
        const float* Arow_r = g_rdup + (size_t)((t + 1) & 1) * (NH * 512) + 2 * m0;
        const float* Arow_x = g_xdup + (size_t)t * ND * 512 + 2 * m0;

        // issue X chunks (independent of state) before the barrier spin
        issueA(0, Arow_x);
        asm volatile("cp.async.commit_group;");
        issueA(1, Arow_x + (size_t)BK * 512);
        asm volatile("cp.async.commit_group;");

        // barrier: wait for all CTAs to have produced state t-1
        if (tid == 0) {
            unsigned int target = (unsigned int)(NCTA * t);
            unsigned int v;
            do {
                asm volatile("ld.acquire.gpu.global.u32 %0, [%1];"
                             : "=r"(v) : "l"(&g_bar));
            } while (v < target);
        }
        __syncthreads();

        unsigned long long az0 = 0, av0 = 0, az1 = 0, av1 = 0;

        int stage = 0;
        for (int it = 0; it < niter; ++it) {
            asm volatile("cp.async.wait_group 1;");
            __syncthreads();
            const int nit = it + 2;
            if (nit < niter) {
                int s2 = stage + 2; if (s2 >= 3) s2 -= 3;
                issueA(s2, Arow_r + (size_t)(nit - 2) * BK * 512);
            }
            asm volatile("cp.async.commit_group;");

            const float* pa = sA + (stage * BK) * 128 + (ty << 2);
            const int kbase = (it < 2) ? (512 + it * BK) : (it - 2) * BK;
            const float* pb = sBf + kbase * BHC + (tx << 2);

            // register double-buffered inner loop over BK (two k per trip)
            ulonglong2 a0 = *(const ulonglong2*)(pa);
            ulonglong2 b0 = *(const ulonglong2*)(pb);
            ulonglong2 a1 = *(const ulonglong2*)(pa + 128);
            ulonglong2 b1 = *(const ulonglong2*)(pb + BHC);
#pragma unroll
            for (int kk = 0; kk < BK; kk += 2) {
                ulonglong2 na0, nb0, na1, nb1;
                if (kk + 2 < BK) {
                    na0 = *(const ulonglong2*)(pa + (kk + 2) * 128);
                    nb0 = *(const ulonglong2*)(pb + (kk + 2) * BHC);
                    na1 = *(const ulonglong2*)(pa + (kk + 3) * 128);
                    nb1 = *(const ulonglong2*)(pb + (kk + 3) * BHC);
                }
                fma2(az0, a0.x, b0.x); fma2(av0, a0.x, b0.y);
                fma2(az1, a0.y, b0.x); fma2(av1, a0.y, b0.y);
                fma2(az0, a1.x, b1.x); fma2(av0, a1.x, b1.y);
                fma2(az1, a1.y, b1.x); fma2(av1, a1.y, b1.y);
                if (kk + 2 < BK) { a0 = na0; b0 = nb0; a1 = na1; b1 = nb1; }
            }
            stage = stage + 1; if (stage >= 3) stage -= 3;
        }

        // ---- epilogue: gate + state update (state in regs) ----
        const float2 azA = u2f(az0), avA = u2f(av0);
        const float2 azB = u2f(az1), avB = u2f(av1);
        const float zA0 = 1.0f / (1.0f + expf(-(azA.x + bz.x)));
        const float zA1 = 1.0f / (1.0f + expf(-(azA.y + bz.y)));
        const float zB0 = 1.0f / (1.0f + expf(-(azB.x + bz.x)));
        const float zB1 = 1.0f / (1.0f + expf(-(azB.y + bz.y)));
        vA0 = (1.0f - zA0) * vA0 + DTF * (avA.x + bv.x);
        vA1 = (1.0f - zA1) * vA1 + DTF * (avA.y + bv.y);
        vB0 = (1.0f - zB0) * vB0 + DTF * (avB.x + bv.x);
        vB1 = (1.0f - zB1) * vB1 + DTF * (avB.y + bv.y);

        *(float2*)&hid[((size_t)mA * NT + t) * NH + hg]       = make_float2(vA0, vA1);
        *(float2*)&hid[((size_t)(mA + 1) * NT + t) * NH + hg] = make_float2(vB0, vB1);

        const float rA0 = fmaxf(vA0, 0.0f), rA1 = fmaxf(vA1, 0.0f);
        const float rB0 = fmaxf(vB0, 0.0f), rB1 = fmaxf(vB1, 0.0f);
        float* rd = g_rdup + (size_t)(t & 1) * (NH * 512);
        *(float4*)&rd[(size_t)hg * 512 + 2 * mA]       = make_float4(rA0, rA0, rB0, rB0);
        *(float4*)&rd[(size_t)(hg + 1) * 512 + 2 * mA] = make_float4(rA1, rA1, rB1, rB1);

        __threadfence();
        __syncthreads();
        if (tid == 0) atomicAdd(&g_bar, 1u);
    }
}

// ---------------------------------------------------------------------------
// FC: out[r][c] = hidden[r][:] . fc_w[c][:] + fc_b[c]
// ---------------------------------------------------------------------------
__global__ void __launch_bounds__(128)
fc_kernel(const float* __restrict__ hid,
          const float* __restrict__ fcb,
          float* __restrict__ out)
{
    __shared__ __align__(16) float fA[2][16][2 * FBM];
    __shared__ __align__(16) float fB[2][16][NC];

    const int tid = threadIdx.x;
    const int m0 = blockIdx.x * FBM;
    const int tx = tid & 7;
    const int ty = tid >> 3;
    const int c0 = tx * 8;

    const int a_m = tid >> 1;
    const int a_k = (tid & 1) * 8;
    const int b_k = tid >> 3;
    const int b_q = (tid & 7) * 8;

    unsigned long long acc[4][4];
#pragma unroll
    for (int i = 0; i < 4; i++)
#pragma unroll
        for (int j = 0; j < 4; j++) acc[i][j] = 0ull;

    auto loadA = [&](int it, float4 &v0, float4 &v1) {
        const float* src = hid + (size_t)(m0 + a_m) * NH + it * 16 + a_k;
        v0 = ((const float4*)src)[0];
        v1 = ((const float4*)src)[1];
    };
    auto loadB = [&](int it, float4 &v0, float4 &v1) {
        const float* src = g_fcT + (size_t)(it * 16 + b_k) * NC + b_q;
        v0 = ((const float4*)src)[0];
        v1 = ((const float4*)src)[1];
    };
    auto stsA = [&](int buf, const float4 &v0, const float4 &v1) {
#pragma unroll
        for (int i = 0; i < 4; i++) {
            float a = (&v0.x)[i];
            *(float2*)&fA[buf][a_k + i][2 * a_m] = make_float2(a, a);
        }
#pragma unroll
        for (int i = 0; i < 4; i++) {
            float a = (&v1.x)[i];
            *(float2*)&fA[buf][a_k + 4 + i][2 * a_m] = make_float2(a, a);
        }
    };
    auto stsB = [&](int buf, const float4 &v0, const float4 &v1) {
        *(float4*)&fB[buf][b_k][b_q]     = v0;
        *(float4*)&fB[buf][b_k][b_q + 4] = v1;
    };

    float4 rA0, rA1, rB0, rB1;
    loadA(0, rA0, rA1); loadB(0, rB0, rB1);
    stsA(0, rA0, rA1); stsB(0, rB0, rB1);
    __syncthreads();

    int cur = 0;
    const int FNITER = NH / 16;
    for (int it = 0; it < FNITER; ++it) {
        const bool more = (it + 1) < FNITER;
        if (more) { loadA(it + 1, rA0, rA1); loadB(it + 1, rB0, rB1); }
#pragma unroll
        for (int kl = 0; kl < 16; ++kl) {
            const ulonglong2 aa0 = *(const ulonglong2*)&fA[cur][kl][8 * ty];
            const ulonglong2 aa1 = *(const ulonglong2*)&fA[cur][kl][8 * ty + 4];
            const ulonglong2 bb0 = *(const ulonglong2*)&fB[cur][kl][c0];
            const ulonglong2 bb1 = *(const ulonglong2*)&fB[cur][kl][c0 + 4];
            fma2(acc[0][0], aa0.x, bb0.x); fma2(acc[0][1], aa0.x, bb0.y);
            fma2(acc[0][2], aa0.x, bb1.x); fma2(acc[0][3], aa0.x, bb1.y);
            fma2(acc[1][0], aa0.y, bb0.x); fma2(acc[1][1], aa0.y, bb0.y);
            fma2(acc[1][2], aa0.y, bb1.x); fma2(acc[1][3], aa0.y, bb1.y);
            fma2(acc[2][0], aa1.x, bb0.x); fma2(acc[2][1], aa1.x, bb0.y);
            fma2(acc[2][2], aa1.x, bb1.x); fma2(acc[2][3], aa1.x, bb1.y);
            fma2(acc[3][0], aa1.y, bb0.x); fma2(acc[3][1], aa1.y, bb0.y);
            fma2(acc[3][2], aa1.y, bb1.x); fma2(acc[3][3], aa1.y, bb1.y);
        }
        if (more) { stsA(cur ^ 1, rA0, rA1); stsB(cur ^ 1, rB0, rB1); }
        __syncthreads();
        cur ^= 1;
    }

    const float4 fb0 = *(const float4*)&fcb[c0];
    const float4 fb1 = *(const float4*)&fcb[c0 + 4];
#pragma unroll
    for (int i = 0; i < 4; i++) {
        const int m = m0 + 4 * ty + i;
        const float2 p0 = u2f(acc[i][0]);
        const float2 p1 = u2f(acc[i][1]);
        const float2 p2 = u2f(acc[i][2]);
        const float2 p3 = u2f(acc[i][3]);
        float4 o0 = make_float4(p0.x + fb0.x, p0.y + fb0.y, p1.x + fb0.z, p1.y + fb0.w);
        float4 o1 = make_float4(p2.x + fb1.x, p2.y + fb1.y, p3.x + fb1.z, p3.y + fb1.w);
        float* dst = out + (size_t)m * NC + c0;
        ((float4*)dst)[0] = o0;
        ((float4*)dst)[1] = o1;
    }
}

// ---------------------------------------------------------------------------
extern "C" void kernel_launch(void* const* d_in, const int* in_sizes, int n_in,
                              void* d_out, int out_size)
{
    const float* x   = (const float*)d_in[0];
    const float* W   = (const float*)d_in[1];
    const float* P   = (const float*)d_in[2];
    const float* b_v = (const float*)d_in[3];
    const float* b_z = (const float*)d_in[4];
    const float* Kw  = (const float*)d_in[5];
    const float* Pz  = (const float*)d_in[6];
    const float* fcw = (const float*)d_in[7];
    const float* fcb = (const float*)d_in[8];

    float* out = (float*)d_out;
    float* hid = out + (size_t)NB * NT * NC;

    (void)in_sizes; (void)n_in; (void)out_size;

    static int smem_set = 0;
    if (!smem_set) {
        cudaFuncSetAttribute(scan_kernel,
                             cudaFuncAttributeMaxDynamicSharedMemorySize, SMEM_BYTES);
        smem_set = 1;
    }

    prep_kernel<<<(576 * 1024 + NH * NC + 255) / 256, 256>>>(W, P, Kw, Pz, fcw);
    prep_xdup<<<dim3(NT, NB / 32), 256>>>(x);

    dim3 sgrid(32, 4);   // 128 CTAs — one wave, persistent
    scan_kernel<<<sgrid, TPB, SMEM_BYTES>>>(b_z, b_v, hid);

    fc_kernel<<<(NB * NT) / FBM, 128>>>(hid, fcb, out);
}

// round 12
// speedup vs baseline: 2.1409x; 1.2590x over previous
#include <cuda_runtime.h>
#include <math.h>
#include <stdint.h>

// Problem dims
#define NB 256
#define NT 512
#define ND 64
#define NH 512
#define NC 64
#define DTF 0.1f

// Scan config: grid (32 h-tiles, 4 m-tiles) = 128 CTAs, 256 threads (2 teams x 128)
#define TPB 256
#define BM 64
#define BK 32
// smem: B [576][32] | A stages 2 teams x 3 x [32][128] | sred 128x8 u64
#define SMEM_B_FLOATS   (576 * 32)
#define SMEM_A_FLOATS   (2 * 3 * BK * 128)
#define SMEM_RED_BYTES  (128 * 8 * 8)
#define SMEM_BYTES      ((SMEM_B_FLOATS + SMEM_A_FLOATS) * 4 + SMEM_RED_BYTES)

// FC tiling
#define FBM 64

// Static scratch
__device__ float g_B[576 * 1024];             // [k][n], n=(h/2)*4+{z0,z1,v0,v1}
__device__ float g_xdup[NT * ND * 2 * NB];    // [t][d][2m]
__device__ float g_rdup[2 * NH * 2 * NB];     // [slot][h][2m]
__device__ float g_fcT[NH * NC];
__device__ unsigned int g_barv[128];          // 4 counters, 128B apart

// ---------------------------------------------------------------------------
__device__ __forceinline__ void fma2(unsigned long long &d,
                                     unsigned long long a,
                                     unsigned long long b) {
    asm("fma.rn.f32x2 %0, %1, %2, %0;" : "+l"(d) : "l"(a), "l"(b));
}
__device__ __forceinline__ unsigned long long add2(unsigned long long a,
                                                   unsigned long long b) {
    unsigned long long r;
    asm("add.rn.f32x2 %0, %1, %2;" : "=l"(r) : "l"(a), "l"(b));
    return r;
}
__device__ __forceinline__ float2 u2f(unsigned long long u) {
    float2 r;
    asm("mov.b64 {%0, %1}, %2;" : "=f"(r.x), "=f"(r.y) : "l"(u));
    return r;
}
__device__ __forceinline__ void cp16(uint32_t dst, const void* src) {
    asm volatile("cp.async.cg.shared.global [%0], [%1], 16;" :: "r"(dst), "l"(src));
}
#define CP_COMMIT() asm volatile("cp.async.commit_group;")
#define BAR_TEAM(id) asm volatile("bar.sync %0, 128;" :: "r"(id) : "memory")

// ---------------------------------------------------------------------------
__global__ void prep_kernel(const float* __restrict__ W,  const float* __restrict__ P,
                            const float* __restrict__ Kw, const float* __restrict__ Pz,
                            const float* __restrict__ fcw) {
    int idx = blockIdx.x * blockDim.x + threadIdx.x;
    if (idx < 128) g_barv[idx] = 0u;
    const int totalB = 576 * 1024;
    if (idx < totalB) {
        int k = idx >> 10;
        int n = idx & 1023;
        int h = ((n >> 2) << 1) | (n & 1);
        bool isv = (n & 2) != 0;
        float val;
        if (k < NH) {
            val = isv ? W[h * NH + k] : Kw[h * NH + k];
        } else {
            int d = k - NH;
            val = isv ? ((h < NH / 2) ? P[h * ND + d] : 0.0f)
                      : Pz[h * ND + d];
        }
        g_B[idx] = val;
    } else {
        int j = idx - totalB;
        if (j < NH * NC) {
            int k = j >> 6;
            int c = j & 63;
            g_fcT[j] = fcw[c * NH + k];
        }
    }
}

__global__ void __launch_bounds__(256)
prep_xdup(const float* __restrict__ x) {
    __shared__ float s[64][33];
    const int t  = blockIdx.x;
    const int m0 = blockIdx.y * 32;
    const int tid = threadIdx.x;
#pragma unroll
    for (int i = 0; i < 8; i++) {
        int idx = tid + i * 256;
        int ml = idx >> 6, d = idx & 63;
        s[d][ml] = x[((size_t)(m0 + ml) * NT + t) * ND + d];
    }
    __syncthreads();
#pragma unroll
    for (int i = 0; i < 8; i++) {
        int idx = tid + i * 256;
        int d = idx >> 5, ml = idx & 31;
        float v = s[d][ml];
        *(float2*)&g_xdup[((size_t)t * ND + d) * 512 + 2 * (m0 + ml)] = make_float2(v, v);
    }
}

// ---------------------------------------------------------------------------
// Persistent scan: 2 k-split teams per CTA, 8 accs/thread, per-group barriers.
// ---------------------------------------------------------------------------
__global__ void __launch_bounds__(TPB)
scan_kernel(const float* __restrict__ bz_g,
            const float* __restrict__ bv_g,
            float* __restrict__ hid)
{
    extern __shared__ float smem[];
    float* sBf = smem;                                   // [576][32]
    float* sA  = smem + SMEM_B_FLOATS;                   // 2 teams x 3 x [32][128]
    unsigned long long* sred =
        (unsigned long long*)(smem + SMEM_B_FLOATS + SMEM_A_FLOATS); // [128][8]

    const int tid  = threadIdx.x;
    const int team = tid >> 7;          // 0 or 1
    const int ttid = tid & 127;
    const int bx   = blockIdx.x;        // h-tile 0..31
    const int by   = blockIdx.y;        // m-tile 0..3
    const int m0   = by * BM;
    const int tx   = ttid & 7;          // h-pair 0..7
    const int ty   = ttid >> 3;         // m-quad 0..15

    unsigned int* ctr = &g_barv[by * 32];

    // ---- load B slice once ----
#pragma unroll
    for (int r = 0; r < 18; r++) {
        int i = tid + r * TPB;
        int row = i >> 3, c = (i & 7) << 2;
        uint32_t dst = (uint32_t)__cvta_generic_to_shared(&sBf[row * 32 + c]);
        cp16(dst, g_B + (size_t)row * 1024 + bx * 32 + c);
    }
    CP_COMMIT();
    asm volatile("cp.async.wait_group 0;");
    __syncthreads();

    const int h2 = bx * 8 + tx;
    const int hg = h2 * 2;
    const float2 bz = *(const float2*)&bz_g[hg];
    const float2 bv = *(const float2*)&bv_g[hg];

    float* sAteam = sA + team * (3 * BK * 128);
    const int barid = 1 + team;

    // v-state (team 0 threads own it): 4 m x (h0,h1)
    float2 vs0 = {0,0}, vs1 = {0,0}, vs2 = {0,0}, vs3 = {0,0};

    // issue one 32-k chunk into a stage
    auto issueChunk = [&](int stg, const float* gbase) {
#pragma unroll
        for (int r = 0; r < 8; r++) {
            int id = ttid + r * 128;
            int kk = id >> 5, c = (id & 31) << 2;
            uint32_t dst = (uint32_t)__cvta_generic_to_shared(
                &sAteam[(stg * BK + kk) * 128 + c]);
            cp16(dst, gbase + (size_t)kk * 512 + c);
        }
        CP_COMMIT();
    };

    unsigned long long az0, az1, az2, az3, av0, av1, av2, av3;

    auto computeChunk = [&](int stg, int kbase) {
        const float* pa = sAteam + (stg * BK) * 128 + ty * 8;
        const float* pb = sBf + kbase * 32 + tx * 4;
        ulonglong2 a0 = *(const ulonglong2*)(pa);
        ulonglong2 a1 = *(const ulonglong2*)(pa + 4);
        ulonglong2 b  = *(const ulonglong2*)(pb);
#pragma unroll
        for (int kk = 0; kk < BK; ++kk) {
            ulonglong2 na0, na1, nb;
            if (kk < BK - 1) {
                na0 = *(const ulonglong2*)(pa + (kk + 1) * 128);
                na1 = *(const ulonglong2*)(pa + (kk + 1) * 128 + 4);
                nb  = *(const ulonglong2*)(pb + (kk + 1) * 32);
            }
            fma2(az0, a0.x, b.x); fma2(av0, a0.x, b.y);
            fma2(az1, a0.y, b.x); fma2(av1, a0.y, b.y);
            fma2(az2, a1.x, b.x); fma2(av2, a1.x, b.y);
            fma2(az3, a1.y, b.x); fma2(av3, a1.y, b.y);
            if (kk < BK - 1) { a0 = na0; a1 = na1; b = nb; }
        }
    };

    // chunk 0 = x (d in [32*team, 32*team+32)); chunks 1..8 = recurrent
    const size_t xoff = (size_t)32 * team * 512 + 2 * m0;
    const size_t roff = (size_t)256 * team * 512 + 2 * m0;
    const int kb_x = 512 + 32 * team;
    const int kb_r = 256 * team;

    // prologue: x chunk for t=0
    issueChunk(0, g_xdup + xoff);

#pragma unroll 1
    for (int t = 0; t < NT; ++t) {
        az0 = az1 = az2 = az3 = 0ull;
        av0 = av1 = av2 = av3 = 0ull;

        // wait for all 32 CTAs of this m-group to finish step t-1
        if (tid == 0) {
            unsigned int target = (unsigned int)(32 * t);
            unsigned int v;
            do {
                asm volatile("ld.acquire.gpu.global.u32 %0, [%1];"
                             : "=r"(v) : "l"(ctr));
            } while (v < target);
        }
        __syncthreads();

        if (t == 0) {
            asm volatile("cp.async.wait_group 0;");
            BAR_TEAM(barid);
            computeChunk(0, kb_x);
        } else {
            const float* rbase = g_rdup + (size_t)((t + 1) & 1) * (NH * 512) + roff;
            issueChunk(1, rbase);                     // chunk 1
#pragma unroll 1
            for (int c = 0; c <= 8; ++c) {
                if (c < 8) { asm volatile("cp.async.wait_group 1;"); }
                else       { asm volatile("cp.async.wait_group 0;"); }
                BAR_TEAM(barid);
                if (c + 2 <= 8)
                    issueChunk((c + 2) % 3, rbase + (size_t)(c + 1) * BK * 512);
                computeChunk(c % 3, (c == 0) ? kb_x : (kb_r + (c - 1) * BK));
            }
        }

        // ---- cross-team reduction ----
        if (team == 1) {
            unsigned long long* d = &sred[ttid * 8];
            *(ulonglong2*)(d)     = make_ulonglong2(az0, av0);
            *(ulonglong2*)(d + 2) = make_ulonglong2(az1, av1);
            *(ulonglong2*)(d + 4) = make_ulonglong2(az2, av2);
            *(ulonglong2*)(d + 6) = make_ulonglong2(az3, av3);
        }
        __syncthreads();

        if (team == 0) {
            const unsigned long long* d = &sred[ttid * 8];
            ulonglong2 q0 = *(const ulonglong2*)(d);
            ulonglong2 q1 = *(const ulonglong2*)(d + 2);
            ulonglong2 q2 = *(const ulonglong2*)(d + 4);
            ulonglong2 q3 = *(const ulonglong2*)(d + 6);
            az0 = add2(az0, q0.x); av0 = add2(av0, q0.y);
            az1 = add2(az1, q1.x); av1 = add2(av1, q1.y);
            az2 = add2(az2, q2.x); av2 = add2(av2, q2.y);
            az3 = add2(az3, q3.x); av3 = add2(av3, q3.y);

            const int mA = m0 + 4 * ty;
            float2 z, v;
            float* rd = g_rdup + (size_t)(t & 1) * (NH * 512);

            z = u2f(az0); v = u2f(av0);
            {
                float s0 = 1.0f / (1.0f + __expf(-(z.x + bz.x)));
                float s1 = 1.0f / (1.0f + __expf(-(z.y + bz.y)));
                vs0.x = (1.0f - s0) * vs0.x + DTF * (v.x + bv.x);
                vs0.y = (1.0f - s1) * vs0.y + DTF * (v.y + bv.y);
            }
            z = u2f(az1); v = u2f(av1);
            {
                float s0 = 1.0f / (1.0f + __expf(-(z.x + bz.x)));
                float s1 = 1.0f / (1.0f + __expf(-(z.y + bz.y)));
                vs1.x = (1.0f - s0) * vs1.x + DTF * (v.x + bv.x);
                vs1.y = (1.0f - s1) * vs1.y + DTF * (v.y + bv.y);
            }
            z = u2f(az2); v = u2f(av2);
            {
                float s0 = 1.0f / (1.0f + __expf(-(z.x + bz.x)));
                float s1 = 1.0f / (1.0f + __expf(-(z.y + bz.y)));
                vs2.x = (1.0f - s0) * vs2.x + DTF * (v.x + bv.x);
                vs2.y = (1.0f - s1) * vs2.y + DTF * (v.y + bv.y);
            }
            z = u2f(az3); v = u2f(av3);
            {
                float s0 = 1.0f / (1.0f + __expf(-(z.x + bz.x)));
                float s1 = 1.0f / (1.0f + __expf(-(z.y + bz.y)));
                vs3.x = (1.0f - s0) * vs3.x + DTF * (v.x + bv.x);
                vs3.y = (1.0f - s1) * vs3.y + DTF * (v.y + bv.y);
            }

            *(float2*)&hid[((size_t)(mA + 0) * NT + t) * NH + hg] = vs0;
            *(float2*)&hid[((size_t)(mA + 1) * NT + t) * NH + hg] = vs1;
            *(float2*)&hid[((size_t)(mA + 2) * NT + t) * NH + hg] = vs2;
            *(float2*)&hid[((size_t)(mA + 3) * NT + t) * NH + hg] = vs3;

            const float r0x = fmaxf(vs0.x, 0.0f), r0y = fmaxf(vs0.y, 0.0f);
            const float r1x = fmaxf(vs1.x, 0.0f), r1y = fmaxf(vs1.y, 0.0f);
            const float r2x = fmaxf(vs2.x, 0.0f), r2y = fmaxf(vs2.y, 0.0f);
            const float r3x = fmaxf(vs3.x, 0.0f), r3y = fmaxf(vs3.y, 0.0f);

            float* sp0 = &rd[(size_t)hg * 512 + 2 * mA];
            ((float4*)sp0)[0] = make_float4(r0x, r0x, r1x, r1x);
            ((float4*)sp0)[1] = make_float4(r2x, r2x, r3x, r3x);
            float* sp1 = &rd[(size_t)(hg + 1) * 512 + 2 * mA];
            ((float4*)sp1)[0] = make_float4(r0y, r0y, r1y, r1y);
            ((float4*)sp1)[1] = make_float4(r2y, r2y, r3y, r3y);

            BAR_TEAM(barid);
            if (tid == 0) {
                __threadfence();
                asm volatile("red.release.gpu.global.add.u32 [%0], %1;"
                             :: "l"(ctr), "r"(1u) : "memory");
            }
        }

        // prefetch x chunk for t+1 (state-independent)
        if (t + 1 < NT)
            issueChunk(0, g_xdup + (size_t)(t + 1) * (ND * 512) + xoff);
    }
}

// ---------------------------------------------------------------------------
// FC (unchanged)
// ---------------------------------------------------------------------------
__global__ void __launch_bounds__(128)
fc_kernel(const float* __restrict__ hid,
          const float* __restrict__ fcb,
          float* __restrict__ out)
{
    __shared__ __align__(16) float fA[2][16][2 * FBM];
    __shared__ __align__(16) float fB[2][16][NC];

    const int tid = threadIdx.x;
    const int m0 = blockIdx.x * FBM;
    const int tx = tid & 7;
    const int ty = tid >> 3;
    const int c0 = tx * 8;

    const int a_m = tid >> 1;
    const int a_k = (tid & 1) * 8;
    const int b_k = tid >> 3;
    const int b_q = (tid & 7) * 8;

    unsigned long long acc[4][4];
#pragma unroll
    for (int i = 0; i < 4; i++)
#pragma unroll
        for (int j = 0; j < 4; j++) acc[i][j] = 0ull;

    auto loadA = [&](int it, float4 &v0, float4 &v1) {
        const float* src = hid + (size_t)(m0 + a_m) * NH + it * 16 + a_k;
        v0 = ((const float4*)src)[0];
        v1 = ((const float4*)src)[1];
    };
    auto loadB = [&](int it, float4 &v0, float4 &v1) {
        const float* src = g_fcT + (size_t)(it * 16 + b_k) * NC + b_q;
        v0 = ((const float4*)src)[0];
        v1 = ((const float4*)src)[1];
    };
    auto stsA = [&](int buf, const float4 &v0, const float4 &v1) {
#pragma unroll
        for (int i = 0; i < 4; i++) {
            float a = (&v0.x)[i];
            *(float2*)&fA[buf][a_k + i][2 * a_m] = make_float2(a, a);
        }
#pragma unroll
        for (int i = 0; i < 4; i++) {
            float a = (&v1.x)[i];
            *(float2*)&fA[buf][a_k + 4 + i][2 * a_m] = make_float2(a, a);
        }
    };
    auto stsB = [&](int buf, const float4 &v0, const float4 &v1) {
        *(float4*)&fB[buf][b_k][b_q]     = v0;
        *(float4*)&fB[buf][b_k][b_q + 4] = v1;
    };

    float4 rA0, rA1, rB0, rB1;
    loadA(0, rA0, rA1); loadB(0, rB0, rB1);
    stsA(0, rA0, rA1); stsB(0, rB0, rB1);
    __syncthreads();

    int cur = 0;
    const int FNITER = NH / 16;
    for (int it = 0; it < FNITER; ++it) {
        const bool more = (it + 1) < FNITER;
        if (more) { loadA(it + 1, rA0, rA1); loadB(it + 1, rB0, rB1); }
#pragma unroll
        for (int kl = 0; kl < 16; ++kl) {
            const ulonglong2 aa0 = *(const ulonglong2*)&fA[cur][kl][8 * ty];
            const ulonglong2 aa1 = *(const ulonglong2*)&fA[cur][kl][8 * ty + 4];
            const ulonglong2 bb0 = *(const ulonglong2*)&fB[cur][kl][c0];
            const ulonglong2 bb1 = *(const ulonglong2*)&fB[cur][kl][c0 + 4];
            fma2(acc[0][0], aa0.x, bb0.x); fma2(acc[0][1], aa0.x, bb0.y);
            fma2(acc[0][2], aa0.x, bb1.x); fma2(acc[0][3], aa0.x, bb1.y);
            fma2(acc[1][0], aa0.y, bb0.x); fma2(acc[1][1], aa0.y, bb0.y);
            fma2(acc[1][2], aa0.y, bb1.x); fma2(acc[1][3], aa0.y, bb1.y);
            fma2(acc[2][0], aa1.x, bb0.x); fma2(acc[2][1], aa1.x, bb0.y);
            fma2(acc[2][2], aa1.x, bb1.x); fma2(acc[2][3], aa1.x, bb1.y);
            fma2(acc[3][0], aa1.y, bb0.x); fma2(acc[3][1], aa1.y, bb0.y);
            fma2(acc[3][2], aa1.y, bb1.x); fma2(acc[3][3], aa1.y, bb1.y);
        }
        if (more) { stsA(cur ^ 1, rA0, rA1); stsB(cur ^ 1, rB0, rB1); }
        __syncthreads();
        cur ^= 1;
    }

    const float4 fb0 = *(const float4*)&fcb[c0];
    const float4 fb1 = *(const float4*)&fcb[c0 + 4];
#pragma unroll
    for (int i = 0; i < 4; i++) {
        const int m = m0 + 4 * ty + i;
        const float2 p0 = u2f(acc[i][0]);
        const float2 p1 = u2f(acc[i][1]);
        const float2 p2 = u2f(acc[i][2]);
        const float2 p3 = u2f(acc[i][3]);
        float4 o0 = make_float4(p0.x + fb0.x, p0.y + fb0.y, p1.x + fb0.z, p1.y + fb0.w);
        float4 o1 = make_float4(p2.x + fb1.x, p2.y + fb1.y, p3.x + fb1.z, p3.y + fb1.w);
        float* dst = out + (size_t)m * NC + c0;
        ((float4*)dst)[0] = o0;
        ((float4*)dst)[1] = o1;
    }
}

// ---------------------------------------------------------------------------
extern "C" void kernel_launch(void* const* d_in, const int* in_sizes, int n_in,
                              void* d_out, int out_size)
{
    const float* x   = (const float*)d_in[0];
    const float* W   = (const float*)d_in[1];
    const float* P   = (const float*)d_in[2];
    const float* b_v = (const float*)d_in[3];
    const float* b_z = (const float*)d_in[4];
    const float* Kw  = (const float*)d_in[5];
    const float* Pz  = (const float*)d_in[6];
    const float* fcw = (const float*)d_in[7];
    const float* fcb = (const float*)d_in[8];

    float* out = (float*)d_out;
    float* hid = out + (size_t)NB * NT * NC;

    (void)in_sizes; (void)n_in; (void)out_size;

    static int smem_set = 0;
    if (!smem_set) {
        cudaFuncSetAttribute(scan_kernel,
                             cudaFuncAttributeMaxDynamicSharedMemorySize, SMEM_BYTES);
        smem_set = 1;
    }

    prep_kernel<<<(576 * 1024 + NH * NC + 255) / 256, 256>>>(W, P, Kw, Pz, fcw);
    prep_xdup<<<dim3(NT, NB / 32), 256>>>(x);

    dim3 sgrid(32, 4);   // 128 CTAs — one wave, persistent
    scan_kernel<<<sgrid, TPB, SMEM_BYTES>>>(b_z, b_v, hid);

    fc_kernel<<<(NB * NT) / FBM, 128>>>(hid, fcb, out);
}